// round 2
// baseline (speedup 1.0000x reference)
#include <cuda_runtime.h>
#include <cstdint>
#include <cstddef>

#define NB 4
#define NS 1024
#define ND 1024
#define NH 16
#define NHD 64

// Scratch (allocation-free rule: __device__ globals)
__device__ float g_qkv[(size_t)NB * NS * 3 * ND];   // 48 MB: [B*S, 3D]  (Q | K | V)
__device__ float g_attn[(size_t)NB * NS * ND];      // 16 MB: [B*S, D]   attention output (heads re-merged)

// ---------------------------------------------------------------------------
// SGEMM: C[M,N] = A[M,K] @ B[K,N] + bias[N], all row-major, fp32.
// 128x128 block tile, BK=16, 256 threads, 8x8 per-thread microtile.
// M,N,K all multiples of tile sizes for this problem -> no bounds checks.
// ---------------------------------------------------------------------------
template<int BM, int BN, int BK>
__global__ __launch_bounds__(256, 2)
void sgemm_bias(const float* __restrict__ A, const float* __restrict__ Bm,
                const float* __restrict__ bias, float* __restrict__ C,
                int M, int N, int K)
{
    __shared__ float As[BK][BM + 4];   // transposed A tile (pad vs store conflicts)
    __shared__ float Bs[BK][BN];

    const int tid  = threadIdx.x;
    const int tx   = tid & 15;         // 16 col-threads
    const int ty   = tid >> 4;         // 16 row-threads
    const int brow = blockIdx.y * BM;
    const int bcol = blockIdx.x * BN;

    float acc[8][8];
    #pragma unroll
    for (int i = 0; i < 8; i++)
        #pragma unroll
        for (int j = 0; j < 8; j++) acc[i][j] = 0.f;

    for (int kt = 0; kt < K; kt += BK) {
        // Cooperative loads: A tile 128x16 (transposed into As), B tile 16x128.
        #pragma unroll
        for (int p = 0; p < 2; p++) {
            int idx = tid + p * 256;               // 0..511
            int ai  = idx >> 2;                    // 0..127
            int ao  = (idx & 3) << 2;              // 0,4,8,12
            float4 av = *(const float4*)&A[(size_t)(brow + ai) * K + kt + ao];
            As[ao + 0][ai] = av.x;
            As[ao + 1][ai] = av.y;
            As[ao + 2][ai] = av.z;
            As[ao + 3][ai] = av.w;
            int bi = idx >> 5;                     // 0..15
            int bo = (idx & 31) << 2;              // 0..124
            *(float4*)&Bs[bi][bo] = *(const float4*)&Bm[(size_t)(kt + bi) * N + bcol + bo];
        }
        __syncthreads();

        #pragma unroll
        for (int k = 0; k < BK; k++) {
            float a[8], b[8];
            *(float4*)&a[0] = *(const float4*)&As[k][ty * 8];
            *(float4*)&a[4] = *(const float4*)&As[k][ty * 8 + 4];
            *(float4*)&b[0] = *(const float4*)&Bs[k][tx * 8];
            *(float4*)&b[4] = *(const float4*)&Bs[k][tx * 8 + 4];
            #pragma unroll
            for (int i = 0; i < 8; i++)
                #pragma unroll
                for (int j = 0; j < 8; j++)
                    acc[i][j] = fmaf(a[i], b[j], acc[i][j]);
        }
        __syncthreads();
    }

    // Epilogue: add bias, vectorized stores.
    float bb[8];
    *(float4*)&bb[0] = *(const float4*)&bias[bcol + tx * 8];
    *(float4*)&bb[4] = *(const float4*)&bias[bcol + tx * 8 + 4];
    #pragma unroll
    for (int i = 0; i < 8; i++) {
        float* cp = C + (size_t)(brow + ty * 8 + i) * N + bcol + tx * 8;
        float4 o0, o1;
        o0.x = acc[i][0] + bb[0]; o0.y = acc[i][1] + bb[1];
        o0.z = acc[i][2] + bb[2]; o0.w = acc[i][3] + bb[3];
        o1.x = acc[i][4] + bb[4]; o1.y = acc[i][5] + bb[5];
        o1.z = acc[i][6] + bb[6]; o1.w = acc[i][7] + bb[7];
        *(float4*)cp       = o0;
        *(float4*)(cp + 4) = o1;
    }
}

// ---------------------------------------------------------------------------
// Fused attention, flash style.
// Grid: (S/64, B*H). Block: 512 threads = 16 warps; each warp owns 4 query rows.
// Per warp-lane: keys (2*lane, 2*lane+1) in QK^T; dims (2*lane, 2*lane+1) in PV.
// Self-attention slot: seeds the online softmax (m0 = s_self, l0 = 1);
// self V contribution added analytically in the epilogue.
// Reference's -10000 mask bias underflows to exactly 0 after softmax in fp32,
// so -1e30 masking is numerically identical.
// ---------------------------------------------------------------------------
#define ATTN_SMEM_FLOATS (64*64 + 64*66 + 64*64 + 64*64)
#define ATTN_SMEM_BYTES  (ATTN_SMEM_FLOATS * 4)

__global__ __launch_bounds__(512, 2)
void attn_kernel(const float* __restrict__ qkv,
                 const float* __restrict__ tk,
                 const float* __restrict__ tv,
                 float* __restrict__ out)
{
    extern __shared__ float sm[];
    float* Qs = sm;              // [64][64]  queries, row-major
    float* Kt = sm + 64 * 64;    // [64][66]  keys, dim-major (padded)
    float* Vs = Kt + 64 * 66;    // [64][64]  values, row-major
    float* Ps = Vs + 64 * 64;    // [64][64]  softmax probs (row-local)

    const int stile = blockIdx.x;          // query tile index
    const int bh    = blockIdx.y;
    const int b     = bh >> 4;
    const int h     = bh & 15;
    const int q0    = stile * 64;
    const int tid   = threadIdx.x;
    const int w     = tid >> 5;
    const int lane  = tid & 31;

    // Load Q tile (64 rows x 64 dims)
    for (int idx = tid; idx < 64 * 64; idx += 512) {
        int r = idx >> 6, d = idx & 63;
        Qs[r * 64 + d] = qkv[(size_t)(b * NS + q0 + r) * (3 * ND) + h * NHD + d];
    }
    __syncthreads();

    const float scale = 0.125f;  // 1/sqrt(64)
    float m[4], l[4], sself[4], acc0[4], acc1[4];

    // Self logit seeds the running softmax state.
    #pragma unroll
    for (int r = 0; r < 4; r++) {
        int row = w * 4 + r;
        const float* kp = qkv + (size_t)(b * NS + q0 + row) * (3 * ND) + ND + h * NHD;
        float2 kv = *(const float2*)(kp + 2 * lane);
        float part = Qs[row * 64 + 2 * lane] * kv.x + Qs[row * 64 + 2 * lane + 1] * kv.y;
        #pragma unroll
        for (int off = 16; off; off >>= 1)
            part += __shfl_xor_sync(0xffffffffu, part, off);
        sself[r] = part * scale;
        m[r] = sself[r];
        l[r] = 1.f;
        acc0[r] = 0.f;
        acc1[r] = 0.f;
    }

    const float* tkb = tk + (size_t)bh * NS * NHD;
    const float* tvb = tv + (size_t)bh * NS * NHD;

    for (int t = 0; t <= stile; t++) {
        __syncthreads();   // previous tile's Kt/Vs/Ps reads complete
        for (int idx = tid; idx < 64 * 64; idx += 512) {
            int j = idx >> 6, d = idx & 63;
            size_t goff = (size_t)(t * 64 + j) * NHD + d;
            Kt[d * 66 + j] = tkb[goff];
            Vs[idx]        = tvb[goff];
        }
        __syncthreads();

        // S = Q K^T : lane owns keys 2*lane, 2*lane+1, for 4 rows.
        float sa[4] = {0, 0, 0, 0}, sb[4] = {0, 0, 0, 0};
        #pragma unroll
        for (int d0 = 0; d0 < 64; d0 += 4) {
            float qv[4][4];
            #pragma unroll
            for (int r = 0; r < 4; r++)
                *(float4*)qv[r] = *(const float4*)(Qs + (w * 4 + r) * 64 + d0);
            #pragma unroll
            for (int dd = 0; dd < 4; dd++) {
                float2 kk = *(const float2*)(Kt + (d0 + dd) * 66 + 2 * lane);
                #pragma unroll
                for (int r = 0; r < 4; r++) {
                    sa[r] = fmaf(qv[r][dd], kk.x, sa[r]);
                    sb[r] = fmaf(qv[r][dd], kk.y, sb[r]);
                }
            }
        }

        // Mask (strict causal: key j visible iff j < q), online softmax update.
        const bool diag = (t == stile);
        #pragma unroll
        for (int r = 0; r < 4; r++) {
            int row = w * 4 + r;   // local row; q index = q0+row, key = t*64+jj
            float va = sa[r] * scale, vb = sb[r] * scale;
            if (diag) {
                if (2 * lane     >= row) va = -1e30f;
                if (2 * lane + 1 >= row) vb = -1e30f;
            }
            float tmx = fmaxf(va, vb);
            #pragma unroll
            for (int off = 16; off; off >>= 1)
                tmx = fmaxf(tmx, __shfl_xor_sync(0xffffffffu, tmx, off));
            float mnew = fmaxf(m[r], tmx);
            float corr = __expf(m[r] - mnew);
            float pa = __expf(va - mnew);
            float pb = __expf(vb - mnew);
            float ps = pa + pb;
            #pragma unroll
            for (int off = 16; off; off >>= 1)
                ps += __shfl_xor_sync(0xffffffffu, ps, off);
            l[r] = l[r] * corr + ps;
            m[r] = mnew;
            acc0[r] *= corr;
            acc1[r] *= corr;
            *(float2*)(Ps + (w * 4 + r) * 64 + 2 * lane) = make_float2(pa, pb);
        }
        __syncwarp();

        // O += P V : lane owns dims 2*lane, 2*lane+1.
        #pragma unroll 2
        for (int j0 = 0; j0 < 64; j0 += 4) {
            float pr[4][4];
            #pragma unroll
            for (int r = 0; r < 4; r++)
                *(float4*)pr[r] = *(const float4*)(Ps + (w * 4 + r) * 64 + j0);
            #pragma unroll
            for (int jj = 0; jj < 4; jj++) {
                float2 vv = *(const float2*)(Vs + (j0 + jj) * 64 + 2 * lane);
                #pragma unroll
                for (int r = 0; r < 4; r++) {
                    acc0[r] = fmaf(pr[r][jj], vv.x, acc0[r]);
                    acc1[r] = fmaf(pr[r][jj], vv.y, acc1[r]);
                }
            }
        }
    }

    // Epilogue: normalize, add self-value contribution, write [B,S,H*HD].
    #pragma unroll
    for (int r = 0; r < 4; r++) {
        int row = w * 4 + r;
        float inv   = 1.f / l[r];
        float wself = __expf(sself[r] - m[r]) * inv;
        const float* vp = qkv + (size_t)(b * NS + q0 + row) * (3 * ND) + 2 * ND + h * NHD;
        float2 vv = *(const float2*)(vp + 2 * lane);
        float o0 = acc0[r] * inv + wself * vv.x;
        float o1 = acc1[r] * inv + wself * vv.y;
        *(float2*)(out + (size_t)(b * NS + q0 + row) * ND + h * NHD + 2 * lane) =
            make_float2(o0, o1);
    }
}

// ---------------------------------------------------------------------------
extern "C" void kernel_launch(void* const* d_in, const int* in_sizes, int n_in,
                              void* d_out, int out_size)
{
    const float* hs = (const float*)d_in[0];   // hidden_states [B,S,D]
    const float* tk = (const float*)d_in[1];   // textual_key   [B,H,S,HD]
    const float* tv = (const float*)d_in[2];   // textual_value [B,H,S,HD]
    const float* Wc = (const float*)d_in[3];   // [D, 3D]
    const float* bc = (const float*)d_in[4];   // [3D]
    const float* Wp = (const float*)d_in[5];   // [D, D]
    const float* bp = (const float*)d_in[6];   // [D]
    float* out = (float*)d_out;

    float *qkv, *attn;
    cudaGetSymbolAddress((void**)&qkv, g_qkv);
    cudaGetSymbolAddress((void**)&attn, g_attn);

    // 1) QKV projection: [4096,1024] @ [1024,3072] + bc
    {
        dim3 grid((3 * ND) / 128, (NB * NS) / 128);
        sgemm_bias<128, 128, 16><<<grid, 256>>>(hs, Wc, bc, qkv, NB * NS, 3 * ND, ND);
    }

    // 2) Fused causal attention + self slot
    {
        cudaFuncSetAttribute(attn_kernel,
                             cudaFuncAttributeMaxDynamicSharedMemorySize,
                             ATTN_SMEM_BYTES);
        dim3 grid(NS / 64, NB * NH);
        attn_kernel<<<grid, 512, ATTN_SMEM_BYTES>>>(qkv, tk, tv, attn);
    }

    // 3) Output projection: [4096,1024] @ [1024,1024] + bp
    {
        dim3 grid(ND / 128, (NB * NS) / 128);
        sgemm_bias<128, 128, 16><<<grid, 256>>>(attn, Wp, bp, out, NB * NS, ND, ND);
    }
}

// round 4
// speedup vs baseline: 1.7608x; 1.7608x over previous
#include <cuda_runtime.h>
#include <cuda_bf16.h>
#include <cstdint>
#include <cstddef>

#define NB 4
#define NS 1024
#define ND 1024
#define NH 16
#define NHD 64
#define K3 3072            // 3 * 1024 : split-K packing (hi*hi + hi*lo + lo*hi)

// ---------------- scratch (allocation-free rule: __device__ globals) -------
__device__ float         g_qkv [(size_t)NB * NS * 3 * ND];     // 48 MB
__device__ float         g_attn[(size_t)NB * NS * ND];         // 16 MB
__device__ __nv_bfloat16 g_a3  [(size_t)NB * NS * K3];         // 25 MB  activations split
__device__ __nv_bfloat16 g_wc3t[(size_t)(3 * ND) * K3];        // 19 MB  Wc^T split
__device__ __nv_bfloat16 g_wp3t[(size_t)ND * K3];              //  6 MB  Wp^T split

// ---------------- PTX helpers (family-portable: no tcgen05) ----------------
__device__ __forceinline__ uint32_t smem_u32(const void* p) {
    uint32_t a;
    asm("{ .reg .u64 t; cvta.to.shared.u64 t, %1; cvt.u32.u64 %0, t; }" : "=r"(a) : "l"(p));
    return a;
}
__device__ __forceinline__ void ldm_x4(uint32_t* r, uint32_t addr) {
    asm volatile("ldmatrix.sync.aligned.m8n8.x4.shared.b16 {%0,%1,%2,%3}, [%4];"
                 : "=r"(r[0]), "=r"(r[1]), "=r"(r[2]), "=r"(r[3]) : "r"(addr));
}
__device__ __forceinline__ void mma16816(float* d, const uint32_t* a, const uint32_t* b) {
    asm volatile(
        "mma.sync.aligned.m16n8k16.row.col.f32.bf16.bf16.f32 "
        "{%0,%1,%2,%3}, {%4,%5,%6,%7}, {%8,%9}, {%0,%1,%2,%3};"
        : "+f"(d[0]), "+f"(d[1]), "+f"(d[2]), "+f"(d[3])
        : "r"(a[0]), "r"(a[1]), "r"(a[2]), "r"(a[3]), "r"(b[0]), "r"(b[1]));
}
#define CP_ASYNC16(smem, gmem) \
    asm volatile("cp.async.cg.shared.global [%0], [%1], 16;" :: "r"(smem), "l"(gmem) : "memory")
#define CP_COMMIT() asm volatile("cp.async.commit_group;" ::: "memory")
#define CP_WAIT1()  asm volatile("cp.async.wait_group 1;" ::: "memory")

__device__ __forceinline__ uint32_t sw128(uint32_t off) {   // XOR swizzle, 128B rows
    return off ^ ((off >> 3) & 0x70);
}

// ---------------------------------------------------------------------------
// Prep 1: split fp32 activations -> bf16 [M, 3K] = [hi | hi | lo]
// ---------------------------------------------------------------------------
__global__ void split_act(const float* __restrict__ in, __nv_bfloat16* __restrict__ out,
                          int M, int K)
{
    size_t i4 = ((size_t)blockIdx.x * blockDim.x + threadIdx.x) * 4;
    if (i4 >= (size_t)M * K) return;
    int r = (int)(i4 / K), c = (int)(i4 % K);
    float4 v = *(const float4*)(in + i4);
    float vv[4] = {v.x, v.y, v.z, v.w};
    __nv_bfloat16 hi[4], lo[4];
    #pragma unroll
    for (int j = 0; j < 4; j++) {
        hi[j] = __float2bfloat16(vv[j]);
        lo[j] = __float2bfloat16(vv[j] - __bfloat162float(hi[j]));
    }
    __nv_bfloat16* o = out + (size_t)r * (3 * K);
    *(__nv_bfloat162*)(o + c)             = __nv_bfloat162(hi[0], hi[1]);
    *(__nv_bfloat162*)(o + c + 2)         = __nv_bfloat162(hi[2], hi[3]);
    *(__nv_bfloat162*)(o + K + c)         = __nv_bfloat162(hi[0], hi[1]);
    *(__nv_bfloat162*)(o + K + c + 2)     = __nv_bfloat162(hi[2], hi[3]);
    *(__nv_bfloat162*)(o + 2 * K + c)     = __nv_bfloat162(lo[0], lo[1]);
    *(__nv_bfloat162*)(o + 2 * K + c + 2) = __nv_bfloat162(lo[2], lo[3]);
}

// ---------------------------------------------------------------------------
// Prep 2: transpose + split weights: W [K,N] fp32 -> Wt3 [N, 3K] bf16 = [hi | lo | hi]
// ---------------------------------------------------------------------------
__global__ void transpose_split(const float* __restrict__ W, __nv_bfloat16* __restrict__ Wt3,
                                int K, int N)
{
    __shared__ float t[32][33];
    int n0 = blockIdx.x * 32, k0 = blockIdx.y * 32;
    int tx = threadIdx.x, ty = threadIdx.y;
    #pragma unroll
    for (int i = 0; i < 32; i += 8)
        t[ty + i][tx] = W[(size_t)(k0 + ty + i) * N + n0 + tx];
    __syncthreads();
    #pragma unroll
    for (int i = 0; i < 32; i += 8) {
        float v = t[tx][ty + i];
        int n = n0 + ty + i, k = k0 + tx;
        __nv_bfloat16 hi = __float2bfloat16(v);
        __nv_bfloat16 lo = __float2bfloat16(v - __bfloat162float(hi));
        __nv_bfloat16* o = Wt3 + (size_t)n * (3 * K);
        o[k]         = hi;
        o[K + k]     = lo;
        o[2 * K + k] = hi;
    }
}

// ---------------------------------------------------------------------------
// bf16 tensor-core GEMM (mma.sync): C[M,N] = A3[M,K3] @ B3t[N,K3]^T + bias[N]
// Block 128x128, BK=64, 8 warps (4x2), warp tile 32x64, 3-stage cp.async.
// ---------------------------------------------------------------------------
#define BM 128
#define BN 128
#define BK 64
#define GT 256
#define KT (K3 / BK)                 // 48 k-tiles
#define STG_A     16384              // 128 rows x 128B
#define STG_BYTES 32768              // A + B per stage
#define SM_BIAS   (3 * STG_BYTES)    // 98304
#define SM_TOTAL  (SM_BIAS + BN * 4)

__global__ __launch_bounds__(GT, 2)
void gemm_mma(const __nv_bfloat16* __restrict__ A, const __nv_bfloat16* __restrict__ B,
              const float* __restrict__ bias, float* __restrict__ C, int N)
{
    extern __shared__ char smem[];
    const uint32_t sb = smem_u32(smem);
    const int tid  = threadIdx.x;
    const int wid  = tid >> 5;
    const int lane = tid & 31;
    const int m0 = blockIdx.y * BM, n0 = blockIdx.x * BN;
    const int warp_m = (wid & 3) * 32;
    const int warp_n = (wid >> 2) * 64;

    float* bias_s = (float*)(smem + SM_BIAS);
    for (int i = tid; i < BN; i += GT) bias_s[i] = bias[n0 + i];

    const char* Ag = (const char*)(A + (size_t)m0 * K3);
    const char* Bg = (const char*)(B + (size_t)n0 * K3);
    const size_t rowb = (size_t)K3 * 2;     // 6144 B per row
    // per-thread gmem chunk: row = tid>>3 (+32*i), 16B chunk c = tid&7
    const int lrow = tid >> 3, lc = (tid & 7) << 4;
    const uint32_t soff = sw128((uint32_t)(lrow * 128 + lc));

    auto load_stage = [&](int kt, int s) {
        const size_t goff = (size_t)lrow * rowb + (size_t)kt * 128 + lc;
        const uint32_t sa = sb + s * STG_BYTES + soff;
        const char* ga = Ag + goff;
        const char* gb = Bg + goff;
        #pragma unroll
        for (int i = 0; i < 4; i++) {
            CP_ASYNC16(sa + i * 4096,           ga + (size_t)i * 32 * rowb);
            CP_ASYNC16(sa + STG_A + i * 4096,   gb + (size_t)i * 32 * rowb);
        }
        CP_COMMIT();
    };

    load_stage(0, 0);
    load_stage(1, 1);

    float d[2][8][4];
    #pragma unroll
    for (int mt = 0; mt < 2; mt++)
        #pragma unroll
        for (int nt = 0; nt < 8; nt++)
            #pragma unroll
            for (int j = 0; j < 4; j++) d[mt][nt][j] = 0.f;

    const int sub = lane >> 3, lr = lane & 7;

    for (int kt = 0; kt < KT; kt++) {
        CP_WAIT1();
        __syncthreads();
        if (kt + 2 < KT) load_stage(kt + 2, (kt + 2) % 3);
        else             CP_COMMIT();            // keep group counting aligned

        const uint32_t a_base = sb + (kt % 3) * STG_BYTES;
        const uint32_t b_base = a_base + STG_A;

        #pragma unroll
        for (int ks = 0; ks < 4; ks++) {
            uint32_t af[2][4];
            #pragma unroll
            for (int mt = 0; mt < 2; mt++) {
                uint32_t off = (uint32_t)((warp_m + mt * 16 + (sub & 1) * 8 + lr) * 128
                                          + ks * 32 + (sub >> 1) * 16);
                ldm_x4(af[mt], a_base + sw128(off));
            }
            uint32_t bf[4][4];
            #pragma unroll
            for (int bt = 0; bt < 4; bt++) {
                uint32_t off = (uint32_t)((warp_n + bt * 16 + (sub >> 1) * 8 + lr) * 128
                                          + ks * 32 + (sub & 1) * 16);
                ldm_x4(bf[bt], b_base + sw128(off));
            }
            #pragma unroll
            for (int mt = 0; mt < 2; mt++)
                #pragma unroll
                for (int nt = 0; nt < 8; nt++)
                    mma16816(d[mt][nt], af[mt], &bf[nt >> 1][(nt & 1) * 2]);
        }
        __syncthreads();
    }

    // Epilogue: bias + fp32 stores (float2 per fragment pair).
    #pragma unroll
    for (int mt = 0; mt < 2; mt++) {
        const int r = m0 + warp_m + mt * 16 + (lane >> 2);
        #pragma unroll
        for (int nt = 0; nt < 8; nt++) {
            const int c = warp_n + nt * 8 + (lane & 3) * 2;
            const float bx = bias_s[c], by = bias_s[c + 1];
            float2 v0 = make_float2(d[mt][nt][0] + bx, d[mt][nt][1] + by);
            float2 v1 = make_float2(d[mt][nt][2] + bx, d[mt][nt][3] + by);
            *(float2*)(C + (size_t)r * N + n0 + c)       = v0;
            *(float2*)(C + (size_t)(r + 8) * N + n0 + c) = v1;
        }
    }
}

// ---------------------------------------------------------------------------
// Fused attention (unchanged — fp32, flash style).
// ---------------------------------------------------------------------------
#define ATTN_SMEM_FLOATS (64*64 + 64*66 + 64*64 + 64*64)
#define ATTN_SMEM_BYTES  (ATTN_SMEM_FLOATS * 4)

__global__ __launch_bounds__(512, 2)
void attn_kernel(const float* __restrict__ qkv,
                 const float* __restrict__ tk,
                 const float* __restrict__ tv,
                 float* __restrict__ out)
{
    extern __shared__ float sm[];
    float* Qs = sm;
    float* Kt = sm + 64 * 64;
    float* Vs = Kt + 64 * 66;
    float* Ps = Vs + 64 * 64;

    const int stile = blockIdx.x;
    const int bh    = blockIdx.y;
    const int b     = bh >> 4;
    const int h     = bh & 15;
    const int q0    = stile * 64;
    const int tid   = threadIdx.x;
    const int w     = tid >> 5;
    const int lane  = tid & 31;

    for (int idx = tid; idx < 64 * 64; idx += 512) {
        int r = idx >> 6, dd = idx & 63;
        Qs[r * 64 + dd] = qkv[(size_t)(b * NS + q0 + r) * (3 * ND) + h * NHD + dd];
    }
    __syncthreads();

    const float scale = 0.125f;
    float m[4], l[4], sself[4], acc0[4], acc1[4];

    #pragma unroll
    for (int r = 0; r < 4; r++) {
        int row = w * 4 + r;
        const float* kp = qkv + (size_t)(b * NS + q0 + row) * (3 * ND) + ND + h * NHD;
        float2 kv = *(const float2*)(kp + 2 * lane);
        float part = Qs[row * 64 + 2 * lane] * kv.x + Qs[row * 64 + 2 * lane + 1] * kv.y;
        #pragma unroll
        for (int off = 16; off; off >>= 1)
            part += __shfl_xor_sync(0xffffffffu, part, off);
        sself[r] = part * scale;
        m[r] = sself[r]; l[r] = 1.f; acc0[r] = 0.f; acc1[r] = 0.f;
    }

    const float* tkb = tk + (size_t)bh * NS * NHD;
    const float* tvb = tv + (size_t)bh * NS * NHD;

    for (int t = 0; t <= stile; t++) {
        __syncthreads();
        for (int idx = tid; idx < 64 * 64; idx += 512) {
            int j = idx >> 6, dd = idx & 63;
            size_t goff = (size_t)(t * 64 + j) * NHD + dd;
            Kt[dd * 66 + j] = tkb[goff];
            Vs[idx]         = tvb[goff];
        }
        __syncthreads();

        float sa[4] = {0, 0, 0, 0}, sb2[4] = {0, 0, 0, 0};
        #pragma unroll
        for (int d0 = 0; d0 < 64; d0 += 4) {
            float qv[4][4];
            #pragma unroll
            for (int r = 0; r < 4; r++)
                *(float4*)qv[r] = *(const float4*)(Qs + (w * 4 + r) * 64 + d0);
            #pragma unroll
            for (int dd = 0; dd < 4; dd++) {
                float2 kk = *(const float2*)(Kt + (d0 + dd) * 66 + 2 * lane);
                #pragma unroll
                for (int r = 0; r < 4; r++) {
                    sa[r]  = fmaf(qv[r][dd], kk.x, sa[r]);
                    sb2[r] = fmaf(qv[r][dd], kk.y, sb2[r]);
                }
            }
        }

        const bool diag = (t == stile);
        #pragma unroll
        for (int r = 0; r < 4; r++) {
            int row = w * 4 + r;
            float va = sa[r] * scale, vb = sb2[r] * scale;
            if (diag) {
                if (2 * lane     >= row) va = -1e30f;
                if (2 * lane + 1 >= row) vb = -1e30f;
            }
            float tmx = fmaxf(va, vb);
            #pragma unroll
            for (int off = 16; off; off >>= 1)
                tmx = fmaxf(tmx, __shfl_xor_sync(0xffffffffu, tmx, off));
            float mnew = fmaxf(m[r], tmx);
            float corr = __expf(m[r] - mnew);
            float pa = __expf(va - mnew);
            float pb = __expf(vb - mnew);
            float ps = pa + pb;
            #pragma unroll
            for (int off = 16; off; off >>= 1)
                ps += __shfl_xor_sync(0xffffffffu, ps, off);
            l[r] = l[r] * corr + ps;
            m[r] = mnew;
            acc0[r] *= corr;
            acc1[r] *= corr;
            *(float2*)(Ps + (w * 4 + r) * 64 + 2 * lane) = make_float2(pa, pb);
        }
        __syncwarp();

        #pragma unroll 2
        for (int j0 = 0; j0 < 64; j0 += 4) {
            float pr[4][4];
            #pragma unroll
            for (int r = 0; r < 4; r++)
                *(float4*)pr[r] = *(const float4*)(Ps + (w * 4 + r) * 64 + j0);
            #pragma unroll
            for (int jj = 0; jj < 4; jj++) {
                float2 vv = *(const float2*)(Vs + (j0 + jj) * 64 + 2 * lane);
                #pragma unroll
                for (int r = 0; r < 4; r++) {
                    acc0[r] = fmaf(pr[r][jj], vv.x, acc0[r]);
                    acc1[r] = fmaf(pr[r][jj], vv.y, acc1[r]);
                }
            }
        }
    }

    #pragma unroll
    for (int r = 0; r < 4; r++) {
        int row = w * 4 + r;
        float inv   = 1.f / l[r];
        float wself = __expf(sself[r] - m[r]) * inv;
        const float* vp = qkv + (size_t)(b * NS + q0 + row) * (3 * ND) + 2 * ND + h * NHD;
        float2 vv = *(const float2*)(vp + 2 * lane);
        float o0 = acc0[r] * inv + wself * vv.x;
        float o1 = acc1[r] * inv + wself * vv.y;
        *(float2*)(out + (size_t)(b * NS + q0 + row) * ND + h * NHD + 2 * lane) =
            make_float2(o0, o1);
    }
}

// ---------------------------------------------------------------------------
extern "C" void kernel_launch(void* const* d_in, const int* in_sizes, int n_in,
                              void* d_out, int out_size)
{
    const float* hs = (const float*)d_in[0];
    const float* tk = (const float*)d_in[1];
    const float* tv = (const float*)d_in[2];
    const float* Wc = (const float*)d_in[3];
    const float* bc = (const float*)d_in[4];
    const float* Wp = (const float*)d_in[5];
    const float* bp = (const float*)d_in[6];
    float* out = (float*)d_out;

    float *qkv, *attn;
    __nv_bfloat16 *a3, *wc3t, *wp3t;
    cudaGetSymbolAddress((void**)&qkv,  g_qkv);
    cudaGetSymbolAddress((void**)&attn, g_attn);
    cudaGetSymbolAddress((void**)&a3,   g_a3);
    cudaGetSymbolAddress((void**)&wc3t, g_wc3t);
    cudaGetSymbolAddress((void**)&wp3t, g_wp3t);

    cudaFuncSetAttribute(gemm_mma, cudaFuncAttributeMaxDynamicSharedMemorySize, SM_TOTAL);
    cudaFuncSetAttribute(attn_kernel, cudaFuncAttributeMaxDynamicSharedMemorySize, ATTN_SMEM_BYTES);

    const int MROWS = NB * NS;   // 4096

    // Prep: split activations + transpose/split both weight matrices.
    split_act<<<(MROWS * ND / 4 + 255) / 256, 256>>>(hs, a3, MROWS, ND);
    transpose_split<<<dim3(3 * ND / 32, ND / 32), dim3(32, 8)>>>(Wc, wc3t, ND, 3 * ND);
    transpose_split<<<dim3(ND / 32, ND / 32), dim3(32, 8)>>>(Wp, wp3t, ND, ND);

    // 1) QKV projection (tensor cores): [4096,3072] = A3 @ Wc3t^T
    gemm_mma<<<dim3(3 * ND / BN, MROWS / BM), GT, SM_TOTAL>>>(a3, wc3t, bc, qkv, 3 * ND);

    // 2) Fused causal attention + self slot
    attn_kernel<<<dim3(NS / 64, NB * NH), 512, ATTN_SMEM_BYTES>>>(qkv, tk, tv, attn);

    // 3) Output projection (tensor cores)
    split_act<<<(MROWS * ND / 4 + 255) / 256, 256>>>(attn, a3, MROWS, ND);
    gemm_mma<<<dim3(ND / BN, MROWS / BM), GT, SM_TOTAL>>>(a3, wp3t, bp, out, ND);
}